// round 1
// baseline (speedup 1.0000x reference)
#include <cuda_runtime.h>
#include <math_constants.h>

#define D_MODEL 1024
#define SEQ     2048
#define BATCH   4
#define NHEADS  16
#define HDIM    64
#define MROWS   (BATCH * SEQ)   // 8192

// Scratch activations (allocation-free rule: __device__ globals)
__device__ float g_q[(size_t)MROWS * D_MODEL];
__device__ float g_k[(size_t)MROWS * D_MODEL];
__device__ float g_v[(size_t)MROWS * D_MODEL];
__device__ float g_attn[(size_t)MROWS * D_MODEL];

// ---------------------------------------------------------------------------
// C[M,N] = A[M,K] @ W[K,N] + bias,  M=8192, K=N=1024
// Block tile 64x64, BK=16, 256 threads, 4x4 register micro-tile per thread.
// ---------------------------------------------------------------------------
__global__ __launch_bounds__(256)
void gemm_bias_kernel(const float* __restrict__ A, const float* __restrict__ W,
                      const float* __restrict__ bias, float* __restrict__ C)
{
    const int K = D_MODEL, N = D_MODEL;
    __shared__ float As[16][64];   // [k][m] (transposed for vector compute loads)
    __shared__ float Ws[16][64];   // [k][n]

    const int tid = threadIdx.x;
    const int tx = tid & 15;        // 0..15 -> n micro
    const int ty = tid >> 4;        // 0..15 -> m micro
    const int bm = blockIdx.y * 64;
    const int bn = blockIdx.x * 64;

    // A tile load mapping: each thread one float4 (row = tid/4, 4 cols)
    const int arow = tid >> 2;          // 0..63
    const int ac   = (tid & 3) * 4;     // 0,4,8,12
    const float* Aptr = A + (size_t)(bm + arow) * K + ac;
    // W tile load mapping: each thread one float4 (row = ty, cols tx*4..)
    const float* Wptr = W + (size_t)ty * N + bn + tx * 4;

    float acc[4][4] = {};

    for (int k0 = 0; k0 < K; k0 += 16) {
        float4 av = *(const float4*)(Aptr + k0);
        float4 wv = *(const float4*)(Wptr + (size_t)k0 * N);
        __syncthreads();
        As[ac + 0][arow] = av.x;
        As[ac + 1][arow] = av.y;
        As[ac + 2][arow] = av.z;
        As[ac + 3][arow] = av.w;
        *(float4*)&Ws[ty][tx * 4] = wv;
        __syncthreads();

#pragma unroll
        for (int kk = 0; kk < 16; ++kk) {
            float4 a = *(const float4*)&As[kk][ty * 4];
            float4 w = *(const float4*)&Ws[kk][tx * 4];
            float ar[4] = {a.x, a.y, a.z, a.w};
            float wr[4] = {w.x, w.y, w.z, w.w};
#pragma unroll
            for (int i = 0; i < 4; ++i)
#pragma unroll
                for (int j = 0; j < 4; ++j)
                    acc[i][j] = fmaf(ar[i], wr[j], acc[i][j]);
        }
    }

    float4 bv = *(const float4*)(bias + bn + tx * 4);
    float br[4] = {bv.x, bv.y, bv.z, bv.w};
#pragma unroll
    for (int i = 0; i < 4; ++i) {
        float4 o;
        o.x = acc[i][0] + br[0];
        o.y = acc[i][1] + br[1];
        o.z = acc[i][2] + br[2];
        o.w = acc[i][3] + br[3];
        *(float4*)&C[(size_t)(bm + ty * 4 + i) * N + bn + tx * 4] = o;
    }
}

// ---------------------------------------------------------------------------
// Flash-style attention: one block = (b, h, 64 q-rows). Streams 64-row K/V
// tiles, online softmax in registers, P tile aliases K's smem (48KB total).
// scores = (Q K^T) / sqrt(64);  O = softmax(scores) V
// ---------------------------------------------------------------------------
__global__ __launch_bounds__(256)
void attn_kernel(const float* __restrict__ Qg, const float* __restrict__ Kg,
                 const float* __restrict__ Vg, float* __restrict__ Og)
{
    __shared__ float Qs [64][64];   // [d][r]  (transposed)
    __shared__ float KPs[64][64];   // K phase: [d][s]; P phase: [r][s]
    __shared__ float Vs [64][64];   // [s][d]

    const int tid = threadIdx.x;
    const int tx = tid & 15;   // s-micro (scores) / d-micro (output)
    const int ty = tid >> 4;   // r-micro
    const int b  = blockIdx.z;
    const int h  = blockIdx.y;
    const int q0 = blockIdx.x * 64;
    const float scale = 0.125f;   // 1/sqrt(64)

    const size_t qbase  = ((size_t)b * SEQ + q0) * D_MODEL + h * HDIM;
    const size_t kvbase = (size_t)b * SEQ * D_MODEL + h * HDIM;

    // Load Q tile transposed: Qs[d][r]
#pragma unroll
    for (int rep = 0; rep < 4; ++rep) {
        int row = ty + rep * 16;    // 0..63
        int c   = tx * 4;
        float4 v = *(const float4*)(Qg + qbase + (size_t)row * D_MODEL + c);
        Qs[c + 0][row] = v.x;
        Qs[c + 1][row] = v.y;
        Qs[c + 2][row] = v.z;
        Qs[c + 3][row] = v.w;
    }

    float m[4], l[4], o[4][4];
#pragma unroll
    for (int i = 0; i < 4; ++i) {
        m[i] = -CUDART_INF_F;
        l[i] = 0.f;
#pragma unroll
        for (int j = 0; j < 4; ++j) o[i][j] = 0.f;
    }

    for (int s0 = 0; s0 < SEQ; s0 += 64) {
        __syncthreads();   // previous PV reads done before overwrite
        // Load K transposed [d][s] and V natural [s][d]
#pragma unroll
        for (int rep = 0; rep < 4; ++rep) {
            int row = ty + rep * 16;
            int c   = tx * 4;
            const float* kp = Kg + kvbase + (size_t)(s0 + row) * D_MODEL + c;
            float4 kv = *(const float4*)kp;
            KPs[c + 0][row] = kv.x;
            KPs[c + 1][row] = kv.y;
            KPs[c + 2][row] = kv.z;
            KPs[c + 3][row] = kv.w;
            const float* vp = Vg + kvbase + (size_t)(s0 + row) * D_MODEL + c;
            *(float4*)&Vs[row][c] = *(const float4*)vp;
        }
        __syncthreads();

        // scores S[r][s] = sum_d Q[r][d] K[s][d]
        float s4[4][4] = {};
#pragma unroll 8
        for (int d = 0; d < 64; ++d) {
            float4 a = *(const float4*)&Qs[d][ty * 4];
            float4 w = *(const float4*)&KPs[d][tx * 4];
            float ar[4] = {a.x, a.y, a.z, a.w};
            float wr[4] = {w.x, w.y, w.z, w.w};
#pragma unroll
            for (int i = 0; i < 4; ++i)
#pragma unroll
                for (int j = 0; j < 4; ++j)
                    s4[i][j] = fmaf(ar[i], wr[j], s4[i][j]);
        }

        __syncthreads();   // everyone done reading K -> KPs becomes P

        // online softmax (row groups are 16 lanes within a half-warp)
#pragma unroll
        for (int i = 0; i < 4; ++i) {
#pragma unroll
            for (int j = 0; j < 4; ++j) s4[i][j] *= scale;
            float tmax = fmaxf(fmaxf(s4[i][0], s4[i][1]), fmaxf(s4[i][2], s4[i][3]));
#pragma unroll
            for (int off = 8; off; off >>= 1)
                tmax = fmaxf(tmax, __shfl_xor_sync(0xffffffffu, tmax, off));
            float mn    = fmaxf(m[i], tmax);
            float alpha = __expf(m[i] - mn);
            float rs = 0.f;
#pragma unroll
            for (int j = 0; j < 4; ++j) {
                float p = __expf(s4[i][j] - mn);
                s4[i][j] = p;
                rs += p;
            }
#pragma unroll
            for (int off = 8; off; off >>= 1)
                rs += __shfl_xor_sync(0xffffffffu, rs, off);
            l[i] = l[i] * alpha + rs;
            m[i] = mn;
#pragma unroll
            for (int j = 0; j < 4; ++j) o[i][j] *= alpha;
        }

        // write P tile [r][s]
#pragma unroll
        for (int i = 0; i < 4; ++i)
            *(float4*)&KPs[ty * 4 + i][tx * 4] =
                make_float4(s4[i][0], s4[i][1], s4[i][2], s4[i][3]);
        __syncthreads();

        // O[r][d] += P[r][s] V[s][d]
#pragma unroll 8
        for (int s = 0; s < 64; ++s) {
            float a0 = KPs[ty * 4 + 0][s];
            float a1 = KPs[ty * 4 + 1][s];
            float a2 = KPs[ty * 4 + 2][s];
            float a3 = KPs[ty * 4 + 3][s];
            float4 w = *(const float4*)&Vs[s][tx * 4];
            float wr[4] = {w.x, w.y, w.z, w.w};
#pragma unroll
            for (int j = 0; j < 4; ++j) {
                o[0][j] = fmaf(a0, wr[j], o[0][j]);
                o[1][j] = fmaf(a1, wr[j], o[1][j]);
                o[2][j] = fmaf(a2, wr[j], o[2][j]);
                o[3][j] = fmaf(a3, wr[j], o[3][j]);
            }
        }
    }

    // normalize + store
#pragma unroll
    for (int i = 0; i < 4; ++i) {
        float inv = 1.f / l[i];
        float4 r;
        r.x = o[i][0] * inv;
        r.y = o[i][1] * inv;
        r.z = o[i][2] * inv;
        r.w = o[i][3] * inv;
        *(float4*)&Og[qbase + (size_t)(ty * 4 + i) * D_MODEL + tx * 4] = r;
    }
}

// ---------------------------------------------------------------------------
extern "C" void kernel_launch(void* const* d_in, const int* in_sizes, int n_in,
                              void* d_out, int out_size)
{
    const float* query = (const float*)d_in[0];
    const float* key   = (const float*)d_in[1];
    const float* value = (const float*)d_in[2];
    const float* Wq = (const float*)d_in[3];
    const float* bq = (const float*)d_in[4];
    const float* Wk = (const float*)d_in[5];
    const float* bk = (const float*)d_in[6];
    const float* Wv = (const float*)d_in[7];
    const float* bv = (const float*)d_in[8];
    const float* Wo = (const float*)d_in[9];
    const float* bo = (const float*)d_in[10];
    float* out = (float*)d_out;

    float *q, *k, *v, *attn;
    cudaGetSymbolAddress((void**)&q,    g_q);
    cudaGetSymbolAddress((void**)&k,    g_k);
    cudaGetSymbolAddress((void**)&v,    g_v);
    cudaGetSymbolAddress((void**)&attn, g_attn);

    dim3 ggrid(D_MODEL / 64, MROWS / 64);   // (16, 128)
    gemm_bias_kernel<<<ggrid, 256>>>(query, Wq, bq, q);
    gemm_bias_kernel<<<ggrid, 256>>>(key,   Wk, bk, k);
    gemm_bias_kernel<<<ggrid, 256>>>(value, Wv, bv, v);

    dim3 agrid(SEQ / 64, NHEADS, BATCH);    // (32, 16, 4)
    attn_kernel<<<agrid, 256>>>(q, k, v, attn);

    gemm_bias_kernel<<<ggrid, 256>>>(attn, Wo, bo, out);
}

// round 3
// speedup vs baseline: 1.5636x; 1.5636x over previous
#include <cuda_runtime.h>
#include <math_constants.h>
#include <cstdint>

#define D_MODEL 1024
#define SEQ     2048
#define BATCH   4
#define NHEADS  16
#define HDIM    64
#define MROWS   (BATCH * SEQ)   // 8192

// Scratch (allocation-free rule: __device__ globals)
__device__ float g_q[(size_t)MROWS * D_MODEL];
__device__ float g_k[(size_t)MROWS * D_MODEL];
__device__ float g_v[(size_t)MROWS * D_MODEL];
__device__ float g_attn[(size_t)MROWS * D_MODEL];
__device__ float g_qc[(size_t)MROWS * D_MODEL];    // tf32-rounded inputs
__device__ float g_kc[(size_t)MROWS * D_MODEL];
__device__ float g_vc[(size_t)MROWS * D_MODEL];
__device__ float g_wt[4][(size_t)D_MODEL * D_MODEL]; // transposed+rounded weights [N][K]

// ---------------------------------------------------------------------------
// helpers
// ---------------------------------------------------------------------------
__device__ __forceinline__ uint32_t smem_u32(const void* p) {
    uint32_t a;
    asm("{ .reg .u64 t; cvta.to.shared.u64 t, %1; cvt.u32.u64 %0, t; }" : "=r"(a) : "l"(p));
    return a;
}
__device__ __forceinline__ uint32_t f2tf(float x) {   // round-to-nearest tf32 (unbiased)
    uint32_t r;
    asm("cvt.rna.tf32.f32 %0, %1;" : "=r"(r) : "f"(x));
    return r;
}
__device__ __forceinline__ void cp16(uint32_t s, const void* g) {
    asm volatile("cp.async.cg.shared.global [%0], [%1], 16;" :: "r"(s), "l"(g));
}
__device__ __forceinline__ void lds32(uint32_t& v, uint32_t a) {
    asm volatile("ld.shared.b32 %0, [%1];" : "=r"(v) : "r"(a));
}
__device__ __forceinline__ void mma_tf32(float* c, const uint32_t* a, const uint32_t* b) {
    asm volatile(
        "mma.sync.aligned.m16n8k8.row.col.f32.tf32.tf32.f32 "
        "{%0,%1,%2,%3}, {%4,%5,%6,%7}, {%8,%9}, {%0,%1,%2,%3};"
        : "+f"(c[0]), "+f"(c[1]), "+f"(c[2]), "+f"(c[3])
        : "r"(a[0]), "r"(a[1]), "r"(a[2]), "r"(a[3]), "r"(b[0]), "r"(b[1]));
}

// ---------------------------------------------------------------------------
// Elementwise tf32-rna convert (float4 grid-stride not needed; exact grid)
// ---------------------------------------------------------------------------
__global__ __launch_bounds__(256)
void cvt_tf32(const float* __restrict__ in, float* __restrict__ out)
{
    size_t i = ((size_t)blockIdx.x * 256 + threadIdx.x) * 4;
    float4 v = *(const float4*)(in + i);
    v.x = __uint_as_float(f2tf(v.x));
    v.y = __uint_as_float(f2tf(v.y));
    v.z = __uint_as_float(f2tf(v.z));
    v.w = __uint_as_float(f2tf(v.w));
    *(float4*)(out + i) = v;
}

// ---------------------------------------------------------------------------
// Transpose + tf32 round: out[n][k] = rna(in[k][n]), 1024x1024
// ---------------------------------------------------------------------------
__global__ __launch_bounds__(256)
void transpose_k(const float* __restrict__ in, float* __restrict__ out)
{
    __shared__ float t[32][33];
    const int bx = blockIdx.x * 32, by = blockIdx.y * 32;
    const int tx = threadIdx.x & 31, ty = threadIdx.x >> 5;
#pragma unroll
    for (int i = 0; i < 4; ++i)
        t[ty + i * 8][tx] = in[(size_t)(by + ty + i * 8) * D_MODEL + bx + tx];
    __syncthreads();
#pragma unroll
    for (int i = 0; i < 4; ++i)
        out[(size_t)(bx + ty + i * 8) * D_MODEL + by + tx] =
            __uint_as_float(f2tf(t[tx][ty + i * 8]));
}

// ---------------------------------------------------------------------------
// mma.sync tf32 GEMM: C[8192,1024] = A @ Bt^T + bias   (Bt is [N][K] = W^T)
// 128x128 tile, BK=32, 8 warps (4x2), 2-stage cp.async double buffer.
// A/Bt must already be tf32-rna-rounded fp32.
// ---------------------------------------------------------------------------
__global__ __launch_bounds__(256)
void gemm_tc(const float* __restrict__ A, const float* __restrict__ Bt,
             const float* __restrict__ bias, float* __restrict__ C)
{
    constexpr int NKT = D_MODEL / 32;         // 32 k-tiles
    extern __shared__ char smem[];
    const uint32_t tb = (smem_u32(smem) + 1023u) & ~1023u;

    const int tid  = threadIdx.x;
    const int wid  = tid >> 5, lane = tid & 31;
    const int wm   = wid & 3,  wn   = wid >> 2;      // warp grid 4(M) x 2(N)
    const int x4   = lane >> 2;                      // 0..7
    const int x4b  = (lane & 3) * 4;                 // byte offset within 16B chunk
    const int bm   = blockIdx.y * 128, bn = blockIdx.x * 128;

    // cp.async mapping: 128 rows x 8 chunks(16B) per operand; 4 chunks/thread
    const int crow = tid >> 3, cch = tid & 7;
    const float* Ag[4]; const float* Bg[4]; uint32_t offs[4];
#pragma unroll
    for (int p = 0; p < 4; ++p) {
        int row = crow + 32 * p;
        Ag[p] = A  + (size_t)(bm + row) * D_MODEL + cch * 4;
        Bg[p] = Bt + (size_t)(bn + row) * D_MODEL + cch * 4;
        offs[p] = (uint32_t)row * 128 + ((uint32_t)(cch ^ (row & 7)) << 4);
    }

    // bias fragment (per n-column pair of each of 8 n-tiles)
    float2 bv[8];
#pragma unroll
    for (int j = 0; j < 8; ++j) {
        int c = bn + wn * 64 + j * 8 + 2 * (lane & 3);
        bv[j] = *(const float2*)(bias + c);
    }

    float acc[2][8][4];
#pragma unroll
    for (int i = 0; i < 2; ++i)
#pragma unroll
        for (int j = 0; j < 8; ++j)
#pragma unroll
            for (int r = 0; r < 4; ++r) acc[i][j][r] = 0.f;

    // prologue: stages 0 and 1
#pragma unroll
    for (int st = 0; st < 2; ++st) {
        uint32_t su = tb + (uint32_t)st * 32768u;
#pragma unroll
        for (int p = 0; p < 4; ++p) {
            cp16(su + offs[p],          Ag[p] + st * 32);
            cp16(su + 16384 + offs[p],  Bg[p] + st * 32);
        }
        asm volatile("cp.async.commit_group;" ::: "memory");
    }

    const uint32_t arow = (uint32_t)(wm * 32 + x4) * 128 + x4b;
    const uint32_t brow = (uint32_t)(wn * 64 + x4) * 128 + x4b;

    for (int kt = 0; kt < NKT; ++kt) {
        asm volatile("cp.async.wait_group 1;" ::: "memory");
        __syncthreads();
        const uint32_t su = tb + (uint32_t)(kt & 1) * 32768u;
        const uint32_t ab = su + arow;
        const uint32_t bb = su + 16384 + brow;

#pragma unroll
        for (int kk = 0; kk < 4; ++kk) {
            const uint32_t xo0 = (uint32_t)((2 * kk) ^ x4) << 4;
            const uint32_t xo1 = (uint32_t)((2 * kk + 1) ^ x4) << 4;
            uint32_t a[2][4], b[8][2];
#pragma unroll
            for (int i = 0; i < 2; ++i) {
                uint32_t r = ab + (uint32_t)(i * 16) * 128;
                lds32(a[i][0], r + xo0);
                lds32(a[i][1], r + 8 * 128 + xo0);
                lds32(a[i][2], r + xo1);
                lds32(a[i][3], r + 8 * 128 + xo1);
            }
#pragma unroll
            for (int j = 0; j < 8; ++j) {
                uint32_t r = bb + (uint32_t)(j * 8) * 128;
                lds32(b[j][0], r + xo0);
                lds32(b[j][1], r + xo1);
            }
#pragma unroll
            for (int i = 0; i < 2; ++i)
#pragma unroll
                for (int j = 0; j < 8; ++j)
                    mma_tf32(acc[i][j], a[i], b[j]);
        }

        __syncthreads();
        if (kt + 2 < NKT) {
            const int k0 = (kt + 2) * 32;
#pragma unroll
            for (int p = 0; p < 4; ++p) {
                cp16(su + offs[p],         Ag[p] + k0);
                cp16(su + 16384 + offs[p], Bg[p] + k0);
            }
            asm volatile("cp.async.commit_group;" ::: "memory");
        } else {
            asm volatile("cp.async.commit_group;" ::: "memory"); // keep group count in step
        }
    }

    // epilogue: direct float2 stores with bias
#pragma unroll
    for (int i = 0; i < 2; ++i) {
        const int r0 = bm + wm * 32 + i * 16 + x4;
#pragma unroll
        for (int j = 0; j < 8; ++j) {
            const int c = bn + wn * 64 + j * 8 + 2 * (lane & 3);
            float2 lo = make_float2(acc[i][j][0] + bv[j].x, acc[i][j][1] + bv[j].y);
            float2 hi = make_float2(acc[i][j][2] + bv[j].x, acc[i][j][3] + bv[j].y);
            *(float2*)(C + (size_t)r0 * D_MODEL + c)       = lo;
            *(float2*)(C + (size_t)(r0 + 8) * D_MODEL + c) = hi;
        }
    }
}

// ---------------------------------------------------------------------------
// Flash-style SIMT attention; output rounded to tf32 for the final tf32 GEMM
// ---------------------------------------------------------------------------
__global__ __launch_bounds__(256)
void attn_kernel(const float* __restrict__ Qg, const float* __restrict__ Kg,
                 const float* __restrict__ Vg, float* __restrict__ Og)
{
    __shared__ float Qs [64][64];
    __shared__ float KPs[64][64];
    __shared__ float Vs [64][64];

    const int tid = threadIdx.x;
    const int tx = tid & 15;
    const int ty = tid >> 4;
    const int b  = blockIdx.z;
    const int h  = blockIdx.y;
    const int q0 = blockIdx.x * 64;
    const float scale = 0.125f;

    const size_t qbase  = ((size_t)b * SEQ + q0) * D_MODEL + h * HDIM;
    const size_t kvbase = (size_t)b * SEQ * D_MODEL + h * HDIM;

#pragma unroll
    for (int rep = 0; rep < 4; ++rep) {
        int row = ty + rep * 16;
        int c   = tx * 4;
        float4 v = *(const float4*)(Qg + qbase + (size_t)row * D_MODEL + c);
        Qs[c + 0][row] = v.x; Qs[c + 1][row] = v.y;
        Qs[c + 2][row] = v.z; Qs[c + 3][row] = v.w;
    }

    float m[4], l[4], o[4][4];
#pragma unroll
    for (int i = 0; i < 4; ++i) {
        m[i] = -CUDART_INF_F; l[i] = 0.f;
#pragma unroll
        for (int j = 0; j < 4; ++j) o[i][j] = 0.f;
    }

    for (int s0 = 0; s0 < SEQ; s0 += 64) {
        __syncthreads();
#pragma unroll
        for (int rep = 0; rep < 4; ++rep) {
            int row = ty + rep * 16;
            int c   = tx * 4;
            float4 kv = *(const float4*)(Kg + kvbase + (size_t)(s0 + row) * D_MODEL + c);
            KPs[c + 0][row] = kv.x; KPs[c + 1][row] = kv.y;
            KPs[c + 2][row] = kv.z; KPs[c + 3][row] = kv.w;
            *(float4*)&Vs[row][c] = *(const float4*)(Vg + kvbase + (size_t)(s0 + row) * D_MODEL + c);
        }
        __syncthreads();

        float s4[4][4] = {};
#pragma unroll 8
        for (int d = 0; d < 64; ++d) {
            float4 a = *(const float4*)&Qs[d][ty * 4];
            float4 w = *(const float4*)&KPs[d][tx * 4];
            float ar[4] = {a.x, a.y, a.z, a.w};
            float wr[4] = {w.x, w.y, w.z, w.w};
#pragma unroll
            for (int i = 0; i < 4; ++i)
#pragma unroll
                for (int j = 0; j < 4; ++j)
                    s4[i][j] = fmaf(ar[i], wr[j], s4[i][j]);
        }

        __syncthreads();

#pragma unroll
        for (int i = 0; i < 4; ++i) {
#pragma unroll
            for (int j = 0; j < 4; ++j) s4[i][j] *= scale;
            float tmax = fmaxf(fmaxf(s4[i][0], s4[i][1]), fmaxf(s4[i][2], s4[i][3]));
#pragma unroll
            for (int off = 8; off; off >>= 1)
                tmax = fmaxf(tmax, __shfl_xor_sync(0xffffffffu, tmax, off));
            float mn    = fmaxf(m[i], tmax);
            float alpha = __expf(m[i] - mn);
            float rs = 0.f;
#pragma unroll
            for (int j = 0; j < 4; ++j) {
                float p = __expf(s4[i][j] - mn);
                s4[i][j] = p; rs += p;
            }
#pragma unroll
            for (int off = 8; off; off >>= 1)
                rs += __shfl_xor_sync(0xffffffffu, rs, off);
            l[i] = l[i] * alpha + rs;
            m[i] = mn;
#pragma unroll
            for (int j = 0; j < 4; ++j) o[i][j] *= alpha;
        }

#pragma unroll
        for (int i = 0; i < 4; ++i)
            *(float4*)&KPs[ty * 4 + i][tx * 4] =
                make_float4(s4[i][0], s4[i][1], s4[i][2], s4[i][3]);
        __syncthreads();

#pragma unroll 8
        for (int s = 0; s < 64; ++s) {
            float a0 = KPs[ty * 4 + 0][s];
            float a1 = KPs[ty * 4 + 1][s];
            float a2 = KPs[ty * 4 + 2][s];
            float a3 = KPs[ty * 4 + 3][s];
            float4 w = *(const float4*)&Vs[s][tx * 4];
            float wr[4] = {w.x, w.y, w.z, w.w};
#pragma unroll
            for (int j = 0; j < 4; ++j) {
                o[0][j] = fmaf(a0, wr[j], o[0][j]);
                o[1][j] = fmaf(a1, wr[j], o[1][j]);
                o[2][j] = fmaf(a2, wr[j], o[2][j]);
                o[3][j] = fmaf(a3, wr[j], o[3][j]);
            }
        }
    }

#pragma unroll
    for (int i = 0; i < 4; ++i) {
        float inv = 1.f / l[i];
        float4 r;
        r.x = __uint_as_float(f2tf(o[i][0] * inv));
        r.y = __uint_as_float(f2tf(o[i][1] * inv));
        r.z = __uint_as_float(f2tf(o[i][2] * inv));
        r.w = __uint_as_float(f2tf(o[i][3] * inv));
        *(float4*)&Og[qbase + (size_t)(ty * 4 + i) * D_MODEL + tx * 4] = r;
    }
}

// ---------------------------------------------------------------------------
extern "C" void kernel_launch(void* const* d_in, const int* in_sizes, int n_in,
                              void* d_out, int out_size)
{
    const float* query = (const float*)d_in[0];
    const float* key   = (const float*)d_in[1];
    const float* value = (const float*)d_in[2];
    const float* Wq = (const float*)d_in[3];
    const float* bq = (const float*)d_in[4];
    const float* Wk = (const float*)d_in[5];
    const float* bk = (const float*)d_in[6];
    const float* Wv = (const float*)d_in[7];
    const float* bv = (const float*)d_in[8];
    const float* Wo = (const float*)d_in[9];
    const float* bo = (const float*)d_in[10];
    float* out = (float*)d_out;

    float *q, *k, *v, *attn, *qc, *kc, *vc, *wt;
    cudaGetSymbolAddress((void**)&q,    g_q);
    cudaGetSymbolAddress((void**)&k,    g_k);
    cudaGetSymbolAddress((void**)&v,    g_v);
    cudaGetSymbolAddress((void**)&attn, g_attn);
    cudaGetSymbolAddress((void**)&qc,   g_qc);
    cudaGetSymbolAddress((void**)&kc,   g_kc);
    cudaGetSymbolAddress((void**)&vc,   g_vc);
    cudaGetSymbolAddress((void**)&wt,   g_wt);
    float* wtq = wt;
    float* wtk = wt + (size_t)D_MODEL * D_MODEL;
    float* wtv = wt + 2 * (size_t)D_MODEL * D_MODEL;
    float* wto = wt + 3 * (size_t)D_MODEL * D_MODEL;

    static const int SMEM_BYTES = 2 * 32768 + 1024;
    cudaFuncSetAttribute(gemm_tc, cudaFuncAttributeMaxDynamicSharedMemorySize, SMEM_BYTES);

    const int cvt_blocks = (MROWS * D_MODEL) / (256 * 4);   // 8192
    cvt_tf32<<<cvt_blocks, 256>>>(query, qc);
    cvt_tf32<<<cvt_blocks, 256>>>(key,   kc);
    cvt_tf32<<<cvt_blocks, 256>>>(value, vc);

    dim3 tgrid(32, 32);
    transpose_k<<<tgrid, 256>>>(Wq, wtq);
    transpose_k<<<tgrid, 256>>>(Wk, wtk);
    transpose_k<<<tgrid, 256>>>(Wv, wtv);
    transpose_k<<<tgrid, 256>>>(Wo, wto);

    dim3 ggrid(D_MODEL / 128, MROWS / 128);   // (8, 64)
    gemm_tc<<<ggrid, 256, SMEM_BYTES>>>(qc, wtq, bq, q);
    gemm_tc<<<ggrid, 256, SMEM_BYTES>>>(kc, wtk, bk, k);
    gemm_tc<<<ggrid, 256, SMEM_BYTES>>>(vc, wtv, bv, v);

    dim3 agrid(SEQ / 64, NHEADS, BATCH);      // (32, 16, 4)
    attn_kernel<<<agrid, 256>>>(q, k, v, attn);

    gemm_tc<<<ggrid, 256, SMEM_BYTES>>>(attn, wto, bo, out);
}

// round 4
// speedup vs baseline: 3.9095x; 2.5003x over previous
#include <cuda_runtime.h>
#include <math_constants.h>
#include <cstdint>

#define D_MODEL 1024
#define SEQ     2048
#define BATCH   4
#define NHEADS  16
#define HDIM    64
#define MROWS   (BATCH * SEQ)   // 8192

// Scratch (allocation-free rule: __device__ globals)
__device__ float g_q[(size_t)MROWS * D_MODEL];
__device__ float g_k[(size_t)MROWS * D_MODEL];
__device__ float g_v[(size_t)MROWS * D_MODEL];
__device__ float g_attn[(size_t)MROWS * D_MODEL];
__device__ float g_qc[(size_t)MROWS * D_MODEL];    // tf32-rounded inputs
__device__ float g_kc[(size_t)MROWS * D_MODEL];
__device__ float g_vc[(size_t)MROWS * D_MODEL];
__device__ float g_wt[4][(size_t)D_MODEL * D_MODEL]; // transposed+rounded weights [N][K]
__device__ float g_vt[(size_t)BATCH * NHEADS * HDIM * SEQ]; // V^T per (b,h): [d][s]

// ---------------------------------------------------------------------------
// helpers
// ---------------------------------------------------------------------------
__device__ __forceinline__ uint32_t smem_u32(const void* p) {
    uint32_t a;
    asm("{ .reg .u64 t; cvta.to.shared.u64 t, %1; cvt.u32.u64 %0, t; }" : "=r"(a) : "l"(p));
    return a;
}
__device__ __forceinline__ uint32_t f2tf(float x) {   // round-to-nearest tf32 (unbiased)
    uint32_t r;
    asm("cvt.rna.tf32.f32 %0, %1;" : "=r"(r) : "f"(x));
    return r;
}
__device__ __forceinline__ void cp16(uint32_t s, const void* g) {
    asm volatile("cp.async.cg.shared.global [%0], [%1], 16;" :: "r"(s), "l"(g));
}
__device__ __forceinline__ void lds32(uint32_t& v, uint32_t a) {
    asm volatile("ld.shared.b32 %0, [%1];" : "=r"(v) : "r"(a));
}
__device__ __forceinline__ void mma_tf32(float* c, const uint32_t* a, const uint32_t* b) {
    asm volatile(
        "mma.sync.aligned.m16n8k8.row.col.f32.tf32.tf32.f32 "
        "{%0,%1,%2,%3}, {%4,%5,%6,%7}, {%8,%9}, {%0,%1,%2,%3};"
        : "+f"(c[0]), "+f"(c[1]), "+f"(c[2]), "+f"(c[3])
        : "r"(a[0]), "r"(a[1]), "r"(a[2]), "r"(a[3]), "r"(b[0]), "r"(b[1]));
}

// ---------------------------------------------------------------------------
// Elementwise tf32-rna convert
// ---------------------------------------------------------------------------
__global__ __launch_bounds__(256)
void cvt_tf32(const float* __restrict__ in, float* __restrict__ out)
{
    size_t i = ((size_t)blockIdx.x * 256 + threadIdx.x) * 4;
    float4 v = *(const float4*)(in + i);
    v.x = __uint_as_float(f2tf(v.x));
    v.y = __uint_as_float(f2tf(v.y));
    v.z = __uint_as_float(f2tf(v.z));
    v.w = __uint_as_float(f2tf(v.w));
    *(float4*)(out + i) = v;
}

// ---------------------------------------------------------------------------
// Transpose + tf32 round: out[n][k] = rna(in[k][n]), 1024x1024
// ---------------------------------------------------------------------------
__global__ __launch_bounds__(256)
void transpose_k(const float* __restrict__ in, float* __restrict__ out)
{
    __shared__ float t[32][33];
    const int bx = blockIdx.x * 32, by = blockIdx.y * 32;
    const int tx = threadIdx.x & 31, ty = threadIdx.x >> 5;
#pragma unroll
    for (int i = 0; i < 4; ++i)
        t[ty + i * 8][tx] = in[(size_t)(by + ty + i * 8) * D_MODEL + bx + tx];
    __syncthreads();
#pragma unroll
    for (int i = 0; i < 4; ++i)
        out[(size_t)(bx + ty + i * 8) * D_MODEL + by + tx] =
            __uint_as_float(f2tf(t[tx][ty + i * 8]));
}

// ---------------------------------------------------------------------------
// V transpose per (b,h): g_vt[(b*16+h)*64 + d][s] = rna(g_v[b][s][h*64+d])
// grid (SEQ/32, HDIM/32, B*H), block (32,8)
// ---------------------------------------------------------------------------
__global__ void transpose_v(const float* __restrict__ v, float* __restrict__ vt)
{
    __shared__ float t[32][33];
    const int bh = blockIdx.z, b = bh >> 4, h = bh & 15;
    const int s0 = blockIdx.x * 32, d0 = blockIdx.y * 32;
    const int tx = threadIdx.x, ty = threadIdx.y;
#pragma unroll
    for (int i = 0; i < 4; ++i)
        t[ty + i * 8][tx] =
            v[((size_t)b * SEQ + s0 + ty + i * 8) * D_MODEL + h * HDIM + d0 + tx];
    __syncthreads();
#pragma unroll
    for (int i = 0; i < 4; ++i)
        vt[((size_t)bh * HDIM + d0 + ty + i * 8) * SEQ + s0 + tx] =
            __uint_as_float(f2tf(t[tx][ty + i * 8]));
}

// ---------------------------------------------------------------------------
// mma.sync tf32 GEMM: C[8192,1024] = A @ Bt^T + bias   (Bt is [N][K] = W^T)
// ---------------------------------------------------------------------------
__global__ __launch_bounds__(256)
void gemm_tc(const float* __restrict__ A, const float* __restrict__ Bt,
             const float* __restrict__ bias, float* __restrict__ C)
{
    constexpr int NKT = D_MODEL / 32;
    extern __shared__ char smem[];
    const uint32_t tb = (smem_u32(smem) + 1023u) & ~1023u;

    const int tid  = threadIdx.x;
    const int wid  = tid >> 5, lane = tid & 31;
    const int wm   = wid & 3,  wn   = wid >> 2;
    const int x4   = lane >> 2;
    const int x4b  = (lane & 3) * 4;
    const int bm   = blockIdx.y * 128, bn = blockIdx.x * 128;

    const int crow = tid >> 3, cch = tid & 7;
    const float* Ag[4]; const float* Bg[4]; uint32_t offs[4];
#pragma unroll
    for (int p = 0; p < 4; ++p) {
        int row = crow + 32 * p;
        Ag[p] = A  + (size_t)(bm + row) * D_MODEL + cch * 4;
        Bg[p] = Bt + (size_t)(bn + row) * D_MODEL + cch * 4;
        offs[p] = (uint32_t)row * 128 + ((uint32_t)(cch ^ (row & 7)) << 4);
    }

    float2 bv[8];
#pragma unroll
    for (int j = 0; j < 8; ++j) {
        int c = bn + wn * 64 + j * 8 + 2 * (lane & 3);
        bv[j] = *(const float2*)(bias + c);
    }

    float acc[2][8][4];
#pragma unroll
    for (int i = 0; i < 2; ++i)
#pragma unroll
        for (int j = 0; j < 8; ++j)
#pragma unroll
            for (int r = 0; r < 4; ++r) acc[i][j][r] = 0.f;

#pragma unroll
    for (int st = 0; st < 2; ++st) {
        uint32_t su = tb + (uint32_t)st * 32768u;
#pragma unroll
        for (int p = 0; p < 4; ++p) {
            cp16(su + offs[p],          Ag[p] + st * 32);
            cp16(su + 16384 + offs[p],  Bg[p] + st * 32);
        }
        asm volatile("cp.async.commit_group;" ::: "memory");
    }

    const uint32_t arow = (uint32_t)(wm * 32 + x4) * 128 + x4b;
    const uint32_t brow = (uint32_t)(wn * 64 + x4) * 128 + x4b;

    for (int kt = 0; kt < NKT; ++kt) {
        asm volatile("cp.async.wait_group 1;" ::: "memory");
        __syncthreads();
        const uint32_t su = tb + (uint32_t)(kt & 1) * 32768u;
        const uint32_t ab = su + arow;
        const uint32_t bb = su + 16384 + brow;

#pragma unroll
        for (int kk = 0; kk < 4; ++kk) {
            const uint32_t xo0 = (uint32_t)((2 * kk) ^ x4) << 4;
            const uint32_t xo1 = (uint32_t)((2 * kk + 1) ^ x4) << 4;
            uint32_t a[2][4], b[8][2];
#pragma unroll
            for (int i = 0; i < 2; ++i) {
                uint32_t r = ab + (uint32_t)(i * 16) * 128;
                lds32(a[i][0], r + xo0);
                lds32(a[i][1], r + 8 * 128 + xo0);
                lds32(a[i][2], r + xo1);
                lds32(a[i][3], r + 8 * 128 + xo1);
            }
#pragma unroll
            for (int j = 0; j < 8; ++j) {
                uint32_t r = bb + (uint32_t)(j * 8) * 128;
                lds32(b[j][0], r + xo0);
                lds32(b[j][1], r + xo1);
            }
#pragma unroll
            for (int i = 0; i < 2; ++i)
#pragma unroll
                for (int j = 0; j < 8; ++j)
                    mma_tf32(acc[i][j], a[i], b[j]);
        }

        __syncthreads();
        if (kt + 2 < NKT) {
            const int k0 = (kt + 2) * 32;
#pragma unroll
            for (int p = 0; p < 4; ++p) {
                cp16(su + offs[p],         Ag[p] + k0);
                cp16(su + 16384 + offs[p], Bg[p] + k0);
            }
        }
        asm volatile("cp.async.commit_group;" ::: "memory");
    }

#pragma unroll
    for (int i = 0; i < 2; ++i) {
        const int r0 = bm + wm * 32 + i * 16 + x4;
#pragma unroll
        for (int j = 0; j < 8; ++j) {
            const int c = bn + wn * 64 + j * 8 + 2 * (lane & 3);
            float2 lo = make_float2(acc[i][j][0] + bv[j].x, acc[i][j][1] + bv[j].y);
            float2 hi = make_float2(acc[i][j][2] + bv[j].x, acc[i][j][3] + bv[j].y);
            *(float2*)(C + (size_t)r0 * D_MODEL + c)       = lo;
            *(float2*)(C + (size_t)(r0 + 8) * D_MODEL + c) = hi;
        }
    }
}

// ---------------------------------------------------------------------------
// Tensor-core flash attention: CTA = (b, h, 64 q rows), 4 warps x m16.
// S = QK^T via mma tf32; fragment online softmax; P -> smem -> PV via mma.
// KP buffer: K tile [s][d] then P tile [q][s]. VT: V^T tile [d][s] (from g_vt).
// Pitch 68 (== 4 mod 32) makes all fragment lds bank-conflict-free.
// ---------------------------------------------------------------------------
__global__ __launch_bounds__(128)
void attn_mma(const float* __restrict__ Qg, const float* __restrict__ Kg,
              const float* __restrict__ Vtg, float* __restrict__ Og)
{
    __shared__ float KP[64][68];
    __shared__ float VT[64][68];
    const int tid = threadIdx.x, lane = tid & 31, wm = tid >> 5;
    const int l4 = lane >> 2, lm = lane & 3;
    const int b = blockIdx.z, h = blockIdx.y, q0 = blockIdx.x * 64;

    const size_t qbase  = ((size_t)b * SEQ + q0) * D_MODEL + h * HDIM;
    const size_t kbase  = (size_t)b * SEQ * D_MODEL + h * HDIM;
    const size_t vtbase = (size_t)(b * NHEADS + h) * HDIM * SEQ;

    // stage Q through smem once; extract tf32-rounded A-fragments for all hd
#pragma unroll
    for (int i = 0; i < 8; ++i) {
        int c = tid + 128 * i, row = c >> 4, ch = c & 15;
        *(float4*)&KP[row][ch * 4] =
            *(const float4*)(Qg + qbase + (size_t)row * D_MODEL + ch * 4);
    }
    __syncthreads();
    uint32_t qf[8][4];
#pragma unroll
    for (int ks = 0; ks < 8; ++ks) {
        qf[ks][0] = f2tf(KP[wm * 16 + l4    ][ks * 8 + lm    ]);
        qf[ks][1] = f2tf(KP[wm * 16 + l4 + 8][ks * 8 + lm    ]);
        qf[ks][2] = f2tf(KP[wm * 16 + l4    ][ks * 8 + lm + 4]);
        qf[ks][3] = f2tf(KP[wm * 16 + l4 + 8][ks * 8 + lm + 4]);
    }
    __syncthreads();

    float of[8][4];
#pragma unroll
    for (int j = 0; j < 8; ++j)
#pragma unroll
        for (int r = 0; r < 4; ++r) of[j][r] = 0.f;
    float m0 = -CUDART_INF_F, m1 = -CUDART_INF_F, ll0 = 0.f, ll1 = 0.f;

    for (int s0 = 0; s0 < SEQ; s0 += 64) {
        // load K tile (round to tf32) and V^T tile (pre-rounded)
#pragma unroll
        for (int i = 0; i < 8; ++i) {
            int c = tid + 128 * i, row = c >> 4, ch = c & 15;
            float4 kv = *(const float4*)(Kg + kbase + (size_t)(s0 + row) * D_MODEL + ch * 4);
            kv.x = __uint_as_float(f2tf(kv.x));
            kv.y = __uint_as_float(f2tf(kv.y));
            kv.z = __uint_as_float(f2tf(kv.z));
            kv.w = __uint_as_float(f2tf(kv.w));
            *(float4*)&KP[row][ch * 4] = kv;
            *(float4*)&VT[row][ch * 4] =
                *(const float4*)(Vtg + vtbase + (size_t)row * SEQ + s0 + ch * 4);
        }
        __syncthreads();

        // S = Q K^T
        float sf[8][4];
#pragma unroll
        for (int j = 0; j < 8; ++j)
#pragma unroll
            for (int r = 0; r < 4; ++r) sf[j][r] = 0.f;
#pragma unroll
        for (int ks = 0; ks < 8; ++ks) {
            uint32_t bq[8][2];
#pragma unroll
            for (int j = 0; j < 8; ++j) {
                bq[j][0] = __float_as_uint(KP[j * 8 + l4][ks * 8 + lm]);
                bq[j][1] = __float_as_uint(KP[j * 8 + l4][ks * 8 + lm + 4]);
            }
#pragma unroll
            for (int j = 0; j < 8; ++j) mma_tf32(sf[j], qf[ks], bq[j]);
        }
        __syncthreads();   // all warps done reading K before P overwrites KP

        // fragment online softmax (rows: l4 and l4+8; quad = lanes xor {1,2})
        float rmax0 = -CUDART_INF_F, rmax1 = -CUDART_INF_F;
#pragma unroll
        for (int j = 0; j < 8; ++j) {
#pragma unroll
            for (int r = 0; r < 4; ++r) sf[j][r] *= 0.125f;
            rmax0 = fmaxf(rmax0, fmaxf(sf[j][0], sf[j][1]));
            rmax1 = fmaxf(rmax1, fmaxf(sf[j][2], sf[j][3]));
        }
#pragma unroll
        for (int off = 1; off <= 2; off <<= 1) {
            rmax0 = fmaxf(rmax0, __shfl_xor_sync(0xffffffffu, rmax0, off));
            rmax1 = fmaxf(rmax1, __shfl_xor_sync(0xffffffffu, rmax1, off));
        }
        const float mn0 = fmaxf(m0, rmax0), mn1 = fmaxf(m1, rmax1);
        const float a0 = __expf(m0 - mn0), a1 = __expf(m1 - mn1);
        float rs0 = 0.f, rs1 = 0.f;
#pragma unroll
        for (int j = 0; j < 8; ++j) {
            sf[j][0] = __expf(sf[j][0] - mn0);
            sf[j][1] = __expf(sf[j][1] - mn0);
            sf[j][2] = __expf(sf[j][2] - mn1);
            sf[j][3] = __expf(sf[j][3] - mn1);
            rs0 += sf[j][0] + sf[j][1];
            rs1 += sf[j][2] + sf[j][3];
        }
#pragma unroll
        for (int off = 1; off <= 2; off <<= 1) {
            rs0 += __shfl_xor_sync(0xffffffffu, rs0, off);
            rs1 += __shfl_xor_sync(0xffffffffu, rs1, off);
        }
        ll0 = ll0 * a0 + rs0;  ll1 = ll1 * a1 + rs1;
        m0 = mn0;  m1 = mn1;
#pragma unroll
        for (int j = 0; j < 8; ++j) {
            of[j][0] *= a0; of[j][1] *= a0;
            of[j][2] *= a1; of[j][3] *= a1;
        }

        // write P (tf32-rounded) into own-warp rows of KP
#pragma unroll
        for (int j = 0; j < 8; ++j) {
            KP[wm * 16 + l4    ][j * 8 + 2 * lm    ] = __uint_as_float(f2tf(sf[j][0]));
            KP[wm * 16 + l4    ][j * 8 + 2 * lm + 1] = __uint_as_float(f2tf(sf[j][1]));
            KP[wm * 16 + l4 + 8][j * 8 + 2 * lm    ] = __uint_as_float(f2tf(sf[j][2]));
            KP[wm * 16 + l4 + 8][j * 8 + 2 * lm + 1] = __uint_as_float(f2tf(sf[j][3]));
        }
        __syncwarp();      // P rows are warp-private

        // O += P V  (A = P from KP, B = V^T from VT)
#pragma unroll
        for (int ks = 0; ks < 8; ++ks) {
            uint32_t ap[4];
            ap[0] = __float_as_uint(KP[wm * 16 + l4    ][ks * 8 + lm    ]);
            ap[1] = __float_as_uint(KP[wm * 16 + l4 + 8][ks * 8 + lm    ]);
            ap[2] = __float_as_uint(KP[wm * 16 + l4    ][ks * 8 + lm + 4]);
            ap[3] = __float_as_uint(KP[wm * 16 + l4 + 8][ks * 8 + lm + 4]);
            uint32_t bv2[8][2];
#pragma unroll
            for (int j = 0; j < 8; ++j) {
                bv2[j][0] = __float_as_uint(VT[j * 8 + l4][ks * 8 + lm]);
                bv2[j][1] = __float_as_uint(VT[j * 8 + l4][ks * 8 + lm + 4]);
            }
#pragma unroll
            for (int j = 0; j < 8; ++j) mma_tf32(of[j], ap, bv2[j]);
        }
        __syncthreads();   // P/VT reads done before next tile load
    }

    // epilogue: normalize, round to tf32 (feeds the tf32 output projection)
    const float inv0 = 1.f / ll0, inv1 = 1.f / ll1;
#pragma unroll
    for (int j = 0; j < 8; ++j) {
        const size_t r0 = (size_t)b * SEQ + q0 + wm * 16 + l4;
        const int col = h * HDIM + j * 8 + 2 * lm;
        float2 lo, hi;
        lo.x = __uint_as_float(f2tf(of[j][0] * inv0));
        lo.y = __uint_as_float(f2tf(of[j][1] * inv0));
        hi.x = __uint_as_float(f2tf(of[j][2] * inv1));
        hi.y = __uint_as_float(f2tf(of[j][3] * inv1));
        *(float2*)(Og + r0 * D_MODEL + col)       = lo;
        *(float2*)(Og + (r0 + 8) * D_MODEL + col) = hi;
    }
}

// ---------------------------------------------------------------------------
extern "C" void kernel_launch(void* const* d_in, const int* in_sizes, int n_in,
                              void* d_out, int out_size)
{
    const float* query = (const float*)d_in[0];
    const float* key   = (const float*)d_in[1];
    const float* value = (const float*)d_in[2];
    const float* Wq = (const float*)d_in[3];
    const float* bq = (const float*)d_in[4];
    const float* Wk = (const float*)d_in[5];
    const float* bk = (const float*)d_in[6];
    const float* Wv = (const float*)d_in[7];
    const float* bv = (const float*)d_in[8];
    const float* Wo = (const float*)d_in[9];
    const float* bo = (const float*)d_in[10];
    float* out = (float*)d_out;

    float *q, *k, *v, *attn, *qc, *kc, *vc, *wt, *vt;
    cudaGetSymbolAddress((void**)&q,    g_q);
    cudaGetSymbolAddress((void**)&k,    g_k);
    cudaGetSymbolAddress((void**)&v,    g_v);
    cudaGetSymbolAddress((void**)&attn, g_attn);
    cudaGetSymbolAddress((void**)&qc,   g_qc);
    cudaGetSymbolAddress((void**)&kc,   g_kc);
    cudaGetSymbolAddress((void**)&vc,   g_vc);
    cudaGetSymbolAddress((void**)&wt,   g_wt);
    cudaGetSymbolAddress((void**)&vt,   g_vt);
    float* wtq = wt;
    float* wtk = wt + (size_t)D_MODEL * D_MODEL;
    float* wtv = wt + 2 * (size_t)D_MODEL * D_MODEL;
    float* wto = wt + 3 * (size_t)D_MODEL * D_MODEL;

    static const int SMEM_BYTES = 2 * 32768 + 1024;
    cudaFuncSetAttribute(gemm_tc, cudaFuncAttributeMaxDynamicSharedMemorySize, SMEM_BYTES);

    const int cvt_blocks = (MROWS * D_MODEL) / (256 * 4);
    cvt_tf32<<<cvt_blocks, 256>>>(query, qc);
    cvt_tf32<<<cvt_blocks, 256>>>(key,   kc);
    cvt_tf32<<<cvt_blocks, 256>>>(value, vc);

    dim3 tgrid(32, 32);
    transpose_k<<<tgrid, 256>>>(Wq, wtq);
    transpose_k<<<tgrid, 256>>>(Wk, wtk);
    transpose_k<<<tgrid, 256>>>(Wv, wtv);
    transpose_k<<<tgrid, 256>>>(Wo, wto);

    dim3 ggrid(D_MODEL / 128, MROWS / 128);
    gemm_tc<<<ggrid, 256, SMEM_BYTES>>>(qc, wtq, bq, q);
    gemm_tc<<<ggrid, 256, SMEM_BYTES>>>(kc, wtk, bk, k);
    gemm_tc<<<ggrid, 256, SMEM_BYTES>>>(vc, wtv, bv, v);

    dim3 vtgrid(SEQ / 32, HDIM / 32, BATCH * NHEADS);
    transpose_v<<<vtgrid, dim3(32, 8)>>>(v, vt);

    dim3 agrid(SEQ / 64, NHEADS, BATCH);
    attn_mma<<<agrid, 128>>>(q, k, vt, attn);

    gemm_tc<<<ggrid, 256, SMEM_BYTES>>>(attn, wto, bo, out);
}